// round 9
// baseline (speedup 1.0000x reference)
#include <cuda_runtime.h>
#include <cuda_fp16.h>
#include <cstdint>

// GraphLearning via mma.sync fp16 (A fp16, B fp16, fp32 accum).
// R9: BM 128->64, 256 thr, occ 2 CTAs/SM -> cross-CTA overlap hides sync/LDG exposure
// that R8 showed to be the binder (halving MMAs only saved 25us).
// hidden_cat = feat @ B, B[d, g*128+h] = att[g,d]*Wlin[g,d,h]
// a_l/a_r fused in epilogue; factors via L2-resident float4 gather (int32 indices).

#define NMAX   100000
#define D_IN   512
#define GDIM   4
#define HDIM   128
#define BM     64
#define KC     32
#define NIT    (D_IN / KC)      // 16
#define ASTR   40               // smem row stride in fp16 elems (80 B) -> conflict-free ldmatrix

// B pre-transposed [g][n][k], fp16 (1 MB, L2-resident)
__device__ __half g_Bh[GDIM * HDIM * D_IN];
__device__ float4 g_al[NMAX];
__device__ float4 g_ar[NMAX];

// ---------------- helpers ----------------
__device__ __forceinline__ uint32_t smem_u32(const void* p) {
    uint32_t a;
    asm("{ .reg .u64 t; cvta.to.shared.u64 t, %1; cvt.u32.u64 %0, t; }" : "=r"(a) : "l"(p));
    return a;
}
__device__ __forceinline__ void ldsm4(uint32_t& r0, uint32_t& r1, uint32_t& r2, uint32_t& r3,
                                      uint32_t addr) {
    asm volatile("ldmatrix.sync.aligned.m8n8.x4.shared.b16 {%0,%1,%2,%3}, [%4];"
                 : "=r"(r0), "=r"(r1), "=r"(r2), "=r"(r3) : "r"(addr));
}
__device__ __forceinline__ void mma16816(float* c, const uint32_t* a, uint32_t b0, uint32_t b1) {
    asm volatile("mma.sync.aligned.m16n8k16.row.col.f32.f16.f16.f32 "
                 "{%0,%1,%2,%3}, {%4,%5,%6,%7}, {%8,%9}, {%0,%1,%2,%3};"
                 : "+f"(c[0]), "+f"(c[1]), "+f"(c[2]), "+f"(c[3])
                 : "r"(a[0]), "r"(a[1]), "r"(a[2]), "r"(a[3]), "r"(b0), "r"(b1));
}
__device__ __forceinline__ uint32_t pack_h2(__half a, __half b) {
    __half2 t; t.x = a; t.y = b;
    return *reinterpret_cast<uint32_t*>(&t);
}

// ---------------- prep: fold att, fp16 round, transpose to [n][k] ----------------
__global__ void prep_kernel(const float* __restrict__ att,
                            const float* __restrict__ Wlin) {
    int i = blockIdx.x * blockDim.x + threadIdx.x;    // [g][d][h] flat
    if (i >= GDIM * D_IN * HDIM) return;
    int g = i >> 16, d = (i >> 7) & 511, n = i & 127;
    float w = att[g * D_IN + d] * Wlin[i];
    g_Bh[(size_t)g * (HDIM * D_IN) + (size_t)n * D_IN + d] = __float2half_rn(w);
}

// ---------------- GEMM: 256 thr, 2(m)x4(n) warps, warp tile m32n32, double-buffered, occ 2 ----
// per-buffer smem: A 64x40 fp16 = 5120 B | B 128x40 fp16 = 10240 B ; x2 buffers = 30720 B
#define T_A  0
#define T_B  5120
#define BUF_SZ 15360
#define SM_SZ  (2 * BUF_SZ)

__global__ __launch_bounds__(256, 2)
void gemm_kernel(const float* __restrict__ feat,
                 const float* __restrict__ b_lin,
                 const float* __restrict__ w_al, const float* __restrict__ b_al,
                 const float* __restrict__ w_ar, const float* __restrict__ b_ar,
                 float* __restrict__ out_hidden, int N) {
    __shared__ __align__(16) char sm[SM_SZ];
    const uint32_t sb = smem_u32(sm);

    const int tid = threadIdx.x, wid = tid >> 5, lid = tid & 31;
    const int wm = wid & 1, wn = wid >> 1;          // warp grid 2(m) x 4(n)
    const int g = blockIdx.x;
    const int row0 = blockIdx.y * BM;

    // A loader: thread -> (row, 8-elem k chunk): 64 rows x 4 thr/row
    const int lrow = tid >> 2;
    const bool rowok = (row0 + lrow) < N;
    const float* abase = feat + (size_t)(row0 + lrow) * D_IN + (tid & 3) * 8;
    const uint32_t sts_a = (uint32_t)lrow * (ASTR * 2) + (uint32_t)(tid & 3) * 16;
    // B loader: thread -> (n-row, 16-elem k half): 128 rows x 2 thr/row
    const int brow = tid >> 1;
    const __half* bbase = g_Bh + (size_t)g * (HDIM * D_IN) + (size_t)brow * D_IN + (tid & 1) * 16;
    const uint32_t sts_b = (uint32_t)brow * (ASTR * 2) + (uint32_t)(tid & 1) * 32;

    // prefetch chunk 0
    float4 pa0 = make_float4(0.f, 0.f, 0.f, 0.f), pa1 = pa0;
    if (rowok) {
        pa0 = *reinterpret_cast<const float4*>(abase);
        pa1 = *reinterpret_cast<const float4*>(abase + 4);
    }
    uint4 pb0 = *reinterpret_cast<const uint4*>(bbase);
    uint4 pb1 = *reinterpret_cast<const uint4*>(bbase + 8);

    float c[2][4][4];
#pragma unroll
    for (int mi = 0; mi < 2; mi++)
#pragma unroll
        for (int ni = 0; ni < 4; ni++)
#pragma unroll
            for (int j = 0; j < 4; j++) c[mi][ni][j] = 0.f;

    const uint32_t lrs = (uint32_t)(lid & 15);      // ldmatrix row select
    const uint32_t lkh = (uint32_t)(lid >> 4);      // k half (16B)

    auto sts_chunk = [&](uint32_t base) {
        uint4 hv = make_uint4(
            pack_h2(__float2half_rn(pa0.x), __float2half_rn(pa0.y)),
            pack_h2(__float2half_rn(pa0.z), __float2half_rn(pa0.w)),
            pack_h2(__float2half_rn(pa1.x), __float2half_rn(pa1.y)),
            pack_h2(__float2half_rn(pa1.z), __float2half_rn(pa1.w)));
        *reinterpret_cast<uint4*>(sm + base + T_A + sts_a) = hv;
        *reinterpret_cast<uint4*>(sm + base + T_B + sts_b) = pb0;
        *reinterpret_cast<uint4*>(sm + base + T_B + sts_b + 16) = pb1;
    };

    sts_chunk(0);
    __syncthreads();

    for (int it = 0; it < NIT; it++) {
        const uint32_t cur = (uint32_t)(it & 1) * BUF_SZ;
        // ---- prefetch next chunk (LDG latency hidden under MMA + co-resident CTA) ----
        if (it + 1 < NIT) {
            int ko = (it + 1) * KC;
            if (rowok) {
                pa0 = *reinterpret_cast<const float4*>(abase + ko);
                pa1 = *reinterpret_cast<const float4*>(abase + ko + 4);
            }
            pb0 = *reinterpret_cast<const uint4*>(bbase + ko);
            pb1 = *reinterpret_cast<const uint4*>(bbase + ko + 8);
        }
        // ---- compute on buffer `cur`: 2 ksteps of 16 ----
#pragma unroll
        for (int ks = 0; ks < 2; ks++) {
            const uint32_t koff = (uint32_t)ks * 32 + lkh * 16;
            uint32_t aA[2][4];
#pragma unroll
            for (int mi = 0; mi < 2; mi++) {
                uint32_t ra = (uint32_t)(wm * 32 + mi * 16) + lrs;
                ldsm4(aA[mi][0], aA[mi][1], aA[mi][2], aA[mi][3],
                      sb + cur + T_A + ra * (ASTR * 2) + koff);
            }
            uint32_t bB[4][2];
#pragma unroll
            for (int p = 0; p < 2; p++) {
                uint32_t rb = (uint32_t)(wn * 32 + p * 16) + lrs;
                uint32_t r0, r1, r2, r3;
                ldsm4(r0, r1, r2, r3, sb + cur + T_B + rb * (ASTR * 2) + koff);
                bB[2 * p][0] = r0; bB[2 * p][1] = r2;
                bB[2 * p + 1][0] = r1; bB[2 * p + 1][1] = r3;
            }
#pragma unroll
            for (int mi = 0; mi < 2; mi++)
#pragma unroll
                for (int ni = 0; ni < 4; ni++)
                    mma16816(c[mi][ni], aA[mi], bB[ni][0], bB[ni][1]);
        }
        // ---- stage next chunk into the other buffer; one sync per iter ----
        if (it + 1 < NIT) {
            sts_chunk(cur ^ BUF_SZ);
            __syncthreads();
        }
    }

    // ---------------- epilogue ----------------
    __syncthreads();                    // all LDSM done; reuse smem for reductions
    float* laR = reinterpret_cast<float*>(sm);            // [4][64]
    float* raR = reinterpret_cast<float*>(sm + 1024);

    const int quad = lid >> 2, tq = lid & 3;
    const float* bl  = b_lin + g * HDIM;
    const float* wal = w_al + g * HDIM;
    const float* war = w_ar + g * HDIM;

#pragma unroll
    for (int mi = 0; mi < 2; mi++)
#pragma unroll
        for (int h = 0; h < 2; h++) {
            int rl = wm * 32 + mi * 16 + h * 8 + quad;
            int rg = row0 + rl;
            bool ok = rg < N;
            float la = 0.f, ra = 0.f;
            float* dst = out_hidden + (size_t)rg * (GDIM * HDIM) + g * HDIM;
#pragma unroll
            for (int ni = 0; ni < 4; ni++) {
                int col = wn * 32 + ni * 8 + tq * 2;
                float v0 = c[mi][ni][h * 2 + 0] + __ldg(bl + col);
                float v1 = c[mi][ni][h * 2 + 1] + __ldg(bl + col + 1);
                la += v0 * __ldg(wal + col) + v1 * __ldg(wal + col + 1);
                ra += v0 * __ldg(war + col) + v1 * __ldg(war + col + 1);
                if (ok) *reinterpret_cast<float2*>(dst + col) = make_float2(v0, v1);
            }
            la += __shfl_xor_sync(0xffffffffu, la, 1);
            la += __shfl_xor_sync(0xffffffffu, la, 2);
            ra += __shfl_xor_sync(0xffffffffu, ra, 1);
            ra += __shfl_xor_sync(0xffffffffu, ra, 2);
            if (tq == 0) { laR[wn * 64 + rl] = la; raR[wn * 64 + rl] = ra; }
        }
    __syncthreads();
    if (tid < 64) {
        int rg = row0 + tid;
        if (rg < N) {
            float la = laR[tid] + laR[64 + tid] + laR[128 + tid] + laR[192 + tid];
            float ra = raR[tid] + raR[64 + tid] + raR[128 + tid] + raR[192 + tid];
            reinterpret_cast<float*>(g_al)[rg * 4 + g] = la + b_al[g];
            reinterpret_cast<float*>(g_ar)[rg * 4 + g] = ra + b_ar[g];
        }
    }
}

// ---------------- edge factors ----------------
__global__ void edge_kernel(const int* __restrict__ src,
                            const int* __restrict__ dst,
                            float* __restrict__ factors, int E, int N) {
    size_t stride = (size_t)gridDim.x * blockDim.x;
    for (size_t e = (size_t)blockIdx.x * blockDim.x + threadIdx.x; e < (size_t)E; e += stride) {
        int s = src[e]; s = s < 0 ? 0 : (s >= N ? N - 1 : s);
        int d = dst[e]; d = d < 0 ? 0 : (d >= N ? N - 1 : d);
        float4 l = g_al[s];
        float4 r = g_ar[d];
        factors[e]                 = 1.f / (1.f + __expf(-(l.x + r.x)));
        factors[(size_t)E + e]     = 1.f / (1.f + __expf(-(l.y + r.y)));
        factors[(size_t)2 * E + e] = 1.f / (1.f + __expf(-(l.z + r.z)));
        factors[(size_t)3 * E + e] = 1.f / (1.f + __expf(-(l.w + r.w)));
    }
}

// ---------------- launch ----------------
extern "C" void kernel_launch(void* const* d_in, const int* in_sizes, int n_in,
                              void* d_out, int out_size) {
    const float* feat  = (const float*)d_in[0];
    const int*   src   = (const int*)d_in[1];
    const int*   dst   = (const int*)d_in[2];
    const float* att   = (const float*)d_in[3];
    const float* Wlin  = (const float*)d_in[4];
    const float* b_lin = (const float*)d_in[5];
    const float* w_al  = (const float*)d_in[6];
    const float* b_al  = (const float*)d_in[7];
    const float* w_ar  = (const float*)d_in[8];
    const float* b_ar  = (const float*)d_in[9];

    int N = in_sizes[0] / D_IN;
    int E = in_sizes[1];
    float* out     = (float*)d_out;
    float* factors = out + (size_t)N * (GDIM * HDIM);

    prep_kernel<<<(GDIM * D_IN * HDIM + 255) / 256, 256>>>(att, Wlin);

    dim3 grid(GDIM, (N + BM - 1) / BM);   // g fastest: CTAs sharing feat rows adjacent in wave
    gemm_kernel<<<grid, 256>>>(feat, b_lin, w_al, b_al, w_ar, b_ar, out, N);

    edge_kernel<<<2048, 256>>>(src, dst, factors, E, N);
}

// round 11
// speedup vs baseline: 1.4147x; 1.4147x over previous
#include <cuda_runtime.h>
#include <cuda_fp16.h>
#include <cstdint>

// GraphLearning, R10: LSU-debt reduction.
//  - feat pre-converted to fp16 once (padded rows -> no guards in GEMM loads)
//  - cp.async 3-stage pipeline for A and B (no STS, no in-loop cvt)
//  - warp tile m64n32 (8 warps, 256 thr, BM=128) -> fewer LDSM per MMA
// hidden_cat = feat @ B, B[d, g*128+h] = att[g,d]*Wlin[g,d,h]; a_l/a_r fused in epilogue.

#define NMAX   100000
#define NPAD   100096           // 782 * 128
#define D_IN   512
#define GDIM   4
#define HDIM   128
#define BM     128
#define KC     32
#define NIT    (D_IN / KC)      // 16
#define ASTRB  80               // smem row stride bytes (40 fp16) -> conflict-free ldmatrix

__device__ __half g_feat_h[(size_t)NPAD * D_IN];     // fp16 features, padded (102.5 MB)
__device__ __half g_Bh[GDIM * HDIM * D_IN];          // B pre-transposed [g][n][k] fp16
__device__ float4 g_al[NMAX];
__device__ float4 g_ar[NMAX];

// ---------------- helpers ----------------
__device__ __forceinline__ uint32_t smem_u32(const void* p) {
    uint32_t a;
    asm("{ .reg .u64 t; cvta.to.shared.u64 t, %1; cvt.u32.u64 %0, t; }" : "=r"(a) : "l"(p));
    return a;
}
__device__ __forceinline__ void ldsm4(uint32_t& r0, uint32_t& r1, uint32_t& r2, uint32_t& r3,
                                      uint32_t addr) {
    asm volatile("ldmatrix.sync.aligned.m8n8.x4.shared.b16 {%0,%1,%2,%3}, [%4];"
                 : "=r"(r0), "=r"(r1), "=r"(r2), "=r"(r3) : "r"(addr));
}
__device__ __forceinline__ void mma16816(float* c, const uint32_t* a, uint32_t b0, uint32_t b1) {
    asm volatile("mma.sync.aligned.m16n8k16.row.col.f32.f16.f16.f32 "
                 "{%0,%1,%2,%3}, {%4,%5,%6,%7}, {%8,%9}, {%0,%1,%2,%3};"
                 : "+f"(c[0]), "+f"(c[1]), "+f"(c[2]), "+f"(c[3])
                 : "r"(a[0]), "r"(a[1]), "r"(a[2]), "r"(a[3]), "r"(b0), "r"(b1));
}
__device__ __forceinline__ void cp16(uint32_t dst, const void* src) {
    asm volatile("cp.async.cg.shared.global [%0], [%1], 16;" :: "r"(dst), "l"(src));
}
#define CP_COMMIT() asm volatile("cp.async.commit_group;" ::: "memory")
#define CP_WAIT1()  asm volatile("cp.async.wait_group 1;" ::: "memory")

__device__ __forceinline__ uint32_t pack_h2(__half a, __half b) {
    __half2 t; t.x = a; t.y = b;
    return *reinterpret_cast<uint32_t*>(&t);
}

// ---------------- convert: feat fp32 -> fp16, zero-pad tail rows ----------------
__global__ void convert_kernel(const float* __restrict__ feat, int N) {
    size_t i = ((size_t)blockIdx.x * blockDim.x + threadIdx.x) * 8;   // 8 elems/thread
    if (i >= (size_t)NPAD * D_IN) return;
    uint4 v = make_uint4(0u, 0u, 0u, 0u);
    if (i < (size_t)N * D_IN) {
        float4 a = *reinterpret_cast<const float4*>(feat + i);
        float4 b = *reinterpret_cast<const float4*>(feat + i + 4);
        v = make_uint4(pack_h2(__float2half_rn(a.x), __float2half_rn(a.y)),
                       pack_h2(__float2half_rn(a.z), __float2half_rn(a.w)),
                       pack_h2(__float2half_rn(b.x), __float2half_rn(b.y)),
                       pack_h2(__float2half_rn(b.z), __float2half_rn(b.w)));
    }
    *reinterpret_cast<uint4*>(g_feat_h + i) = v;
}

// ---------------- prep: fold att, fp16 round, transpose to [n][k] ----------------
__global__ void prep_kernel(const float* __restrict__ att,
                            const float* __restrict__ Wlin) {
    int i = blockIdx.x * blockDim.x + threadIdx.x;    // [g][d][h] flat
    if (i >= GDIM * D_IN * HDIM) return;
    int g = i >> 16, d = (i >> 7) & 511, n = i & 127;
    float w = att[g * D_IN + d] * Wlin[i];
    g_Bh[(size_t)g * (HDIM * D_IN) + (size_t)n * D_IN + d] = __float2half_rn(w);
}

// ---------------- GEMM: 256 thr, 2(m)x4(n) warps, warp tile m64n32, cp.async 3-stage ----
// stage: A 128x80B = 10240 | B 128x80B = 10240 -> 20480/stage, 3 stages = 61440 B
#define STG_SZ 20480
#define T_B    10240
#define SM_SZ  (3 * STG_SZ)

__global__ __launch_bounds__(256, 2)
void gemm_kernel(const float* __restrict__ b_lin,
                 const float* __restrict__ w_al, const float* __restrict__ b_al,
                 const float* __restrict__ w_ar, const float* __restrict__ b_ar,
                 float* __restrict__ out_hidden, int N) {
    extern __shared__ __align__(16) char sm[];
    const uint32_t sb = smem_u32(sm);

    const int tid = threadIdx.x, wid = tid >> 5, lid = tid & 31;
    const int wm = wid & 1, wn = wid >> 1;          // warp grid 2(m) x 4(n)
    const int g = blockIdx.x;
    const int row0 = blockIdx.y * BM;

    // loader mapping: unit u -> (row = u>>2, 16B quarter q = u&3); 512 units per tile
    const int lr0 = tid >> 2, lq = tid & 3;
    const __half* asrc = g_feat_h + (size_t)(row0 + lr0) * D_IN + lq * 8;
    const __half* asrc2 = asrc + (size_t)64 * D_IN;                 // rows 64..127
    const __half* bsrc = g_Bh + (size_t)g * (HDIM * D_IN) + (size_t)lr0 * D_IN + lq * 8;
    const __half* bsrc2 = bsrc + (size_t)64 * D_IN;
    const uint32_t dA1 = (uint32_t)lr0 * ASTRB + (uint32_t)lq * 16;
    const uint32_t dA2 = dA1 + 64 * ASTRB;

    auto issue = [&](int kchunk, uint32_t base) {
        int ko = kchunk * KC;
        cp16(base + dA1,       asrc  + ko);
        cp16(base + dA2,       asrc2 + ko);
        cp16(base + T_B + dA1, bsrc  + ko);
        cp16(base + T_B + dA2, bsrc2 + ko);
    };

    // preload stages 0,1
    issue(0, sb);            CP_COMMIT();
    issue(1, sb + STG_SZ);   CP_COMMIT();

    float c[4][4][4];
#pragma unroll
    for (int mi = 0; mi < 4; mi++)
#pragma unroll
        for (int ni = 0; ni < 4; ni++)
#pragma unroll
            for (int j = 0; j < 4; j++) c[mi][ni][j] = 0.f;

    const uint32_t lrs = (uint32_t)(lid & 15);      // ldmatrix row select
    const uint32_t lkh = (uint32_t)(lid >> 4) * 16; // k half offset (bytes)

    int bufidx = 0;
    for (int it = 0; it < NIT; it++) {
        CP_WAIT1();
        __syncthreads();
        const uint32_t cur = sb + (uint32_t)bufidx * STG_SZ;
        // issue stage it+2 into the buffer freed at iter it-1
        if (it + 2 < NIT) {
            int nb = bufidx + 2; if (nb >= 3) nb -= 3;
            issue(it + 2, sb + (uint32_t)nb * STG_SZ);
        }
        CP_COMMIT();                                 // uniform group counting (may be empty)
        // compute: 2 ksteps of 16
#pragma unroll
        for (int ks = 0; ks < 2; ks++) {
            const uint32_t koff = (uint32_t)ks * 32 + lkh;
            uint32_t aA[4][4];
#pragma unroll
            for (int mi = 0; mi < 4; mi++) {
                uint32_t ra = (uint32_t)(wm * 64 + mi * 16) + lrs;
                ldsm4(aA[mi][0], aA[mi][1], aA[mi][2], aA[mi][3],
                      cur + ra * ASTRB + koff);
            }
            uint32_t bB[4][2];
#pragma unroll
            for (int p = 0; p < 2; p++) {
                uint32_t rb = (uint32_t)(wn * 32 + p * 16) + lrs;
                uint32_t r0, r1, r2, r3;
                ldsm4(r0, r1, r2, r3, cur + T_B + rb * ASTRB + koff);
                bB[2 * p][0] = r0; bB[2 * p][1] = r2;
                bB[2 * p + 1][0] = r1; bB[2 * p + 1][1] = r3;
            }
#pragma unroll
            for (int mi = 0; mi < 4; mi++)
#pragma unroll
                for (int ni = 0; ni < 4; ni++)
                    mma16816(c[mi][ni], aA[mi], bB[ni][0], bB[ni][1]);
        }
        if (++bufidx == 3) bufidx = 0;
    }

    // ---------------- epilogue ----------------
    __syncthreads();                    // all LDSM done; reuse smem for reductions
    float* laR = reinterpret_cast<float*>(sm);            // [4][128]
    float* raR = reinterpret_cast<float*>(sm + 2048);

    const int quad = lid >> 2, tq = lid & 3;
    const float* bl  = b_lin + g * HDIM;
    const float* wal = w_al + g * HDIM;
    const float* war = w_ar + g * HDIM;

#pragma unroll
    for (int mi = 0; mi < 4; mi++)
#pragma unroll
        for (int h = 0; h < 2; h++) {
            int rl = wm * 64 + mi * 16 + h * 8 + quad;
            int rg = row0 + rl;
            bool ok = rg < N;
            float la = 0.f, ra = 0.f;
            float* dst = out_hidden + (size_t)rg * (GDIM * HDIM) + g * HDIM;
#pragma unroll
            for (int ni = 0; ni < 4; ni++) {
                int col = wn * 32 + ni * 8 + tq * 2;
                float v0 = c[mi][ni][h * 2 + 0] + __ldg(bl + col);
                float v1 = c[mi][ni][h * 2 + 1] + __ldg(bl + col + 1);
                la += v0 * __ldg(wal + col) + v1 * __ldg(wal + col + 1);
                ra += v0 * __ldg(war + col) + v1 * __ldg(war + col + 1);
                if (ok) *reinterpret_cast<float2*>(dst + col) = make_float2(v0, v1);
            }
            la += __shfl_xor_sync(0xffffffffu, la, 1);
            la += __shfl_xor_sync(0xffffffffu, la, 2);
            ra += __shfl_xor_sync(0xffffffffu, ra, 1);
            ra += __shfl_xor_sync(0xffffffffu, ra, 2);
            if (tq == 0) { laR[wn * 128 + rl] = la; raR[wn * 128 + rl] = ra; }
        }
    __syncthreads();
    if (tid < 128) {
        int rg = row0 + tid;
        if (rg < N) {
            float la = laR[tid] + laR[128 + tid] + laR[256 + tid] + laR[384 + tid];
            float ra = raR[tid] + raR[128 + tid] + raR[256 + tid] + raR[384 + tid];
            reinterpret_cast<float*>(g_al)[rg * 4 + g] = la + b_al[g];
            reinterpret_cast<float*>(g_ar)[rg * 4 + g] = ra + b_ar[g];
        }
    }
}

// ---------------- edge factors ----------------
__global__ void edge_kernel(const int* __restrict__ src,
                            const int* __restrict__ dst,
                            float* __restrict__ factors, int E, int N) {
    size_t stride = (size_t)gridDim.x * blockDim.x;
    for (size_t e = (size_t)blockIdx.x * blockDim.x + threadIdx.x; e < (size_t)E; e += stride) {
        int s = src[e]; s = s < 0 ? 0 : (s >= N ? N - 1 : s);
        int d = dst[e]; d = d < 0 ? 0 : (d >= N ? N - 1 : d);
        float4 l = g_al[s];
        float4 r = g_ar[d];
        factors[e]                 = 1.f / (1.f + __expf(-(l.x + r.x)));
        factors[(size_t)E + e]     = 1.f / (1.f + __expf(-(l.y + r.y)));
        factors[(size_t)2 * E + e] = 1.f / (1.f + __expf(-(l.z + r.z)));
        factors[(size_t)3 * E + e] = 1.f / (1.f + __expf(-(l.w + r.w)));
    }
}

// ---------------- launch ----------------
extern "C" void kernel_launch(void* const* d_in, const int* in_sizes, int n_in,
                              void* d_out, int out_size) {
    const float* feat  = (const float*)d_in[0];
    const int*   src   = (const int*)d_in[1];
    const int*   dst   = (const int*)d_in[2];
    const float* att   = (const float*)d_in[3];
    const float* Wlin  = (const float*)d_in[4];
    const float* b_lin = (const float*)d_in[5];
    const float* w_al  = (const float*)d_in[6];
    const float* b_al  = (const float*)d_in[7];
    const float* w_ar  = (const float*)d_in[8];
    const float* b_ar  = (const float*)d_in[9];

    int N = in_sizes[0] / D_IN;
    int E = in_sizes[1];
    float* out     = (float*)d_out;
    float* factors = out + (size_t)N * (GDIM * HDIM);

    cudaFuncSetAttribute(gemm_kernel, cudaFuncAttributeMaxDynamicSharedMemorySize, SM_SZ);

    convert_kernel<<<(int)(((size_t)NPAD * D_IN / 8 + 255) / 256), 256>>>(feat, N);
    prep_kernel<<<(GDIM * D_IN * HDIM + 255) / 256, 256>>>(att, Wlin);

    dim3 grid(GDIM, (NPAD + BM - 1) / BM);   // g fastest: CTAs sharing feat rows adjacent in wave
    gemm_kernel<<<grid, 256, SM_SZ>>>(b_lin, w_al, b_al, w_ar, b_ar, out, N);

    edge_kernel<<<2048, 256>>>(src, dst, factors, E, N);
}